// round 4
// baseline (speedup 1.0000x reference)
#include <cuda_runtime.h>

#define N_NODES 100000
#define N_EDGES 1600000
#define D 128
#define N_LAYERS 4
#define N_GRAPHS 512

// ---------------- device scratch (no allocations allowed) ----------------
__device__ float g_xw[N_NODES * D];       // XW buffer (51.2 MB)
__device__ float g_h[N_NODES * D];        // aggregated hidden (51.2 MB)
__device__ float g_dinv[N_NODES];
__device__ int   g_cnt[N_NODES];
__device__ int   g_rowptr[N_NODES + 1];
__device__ int   g_cursor[N_NODES];
__device__ int   g_bsum[512];
__device__ int   g_src[N_EDGES];          // CSR (by destination) source ids

// ---------------- CSR build ----------------
__global__ void zero_cnt_kernel() {
    int i = blockIdx.x * blockDim.x + threadIdx.x;
    if (i < N_NODES) g_cnt[i] = 0;
}

__device__ __forceinline__ int clampi(int v, int hi) {
    return v < 0 ? 0 : (v >= hi ? hi - 1 : v);
}

__global__ void count_kernel(const int* __restrict__ col) {
    int e = blockIdx.x * blockDim.x + threadIdx.x;
    if (e < N_EDGES) atomicAdd(&g_cnt[clampi(col[e], N_NODES)], 1);
}

// Per-block inclusive scan (256 elems), writes local-exclusive into rowptr, block sum to bsum
__global__ void scan1_kernel() {
    __shared__ int s[256];
    int t = threadIdx.x;
    int i = blockIdx.x * 256 + t;
    int v = (i < N_NODES) ? g_cnt[i] : 0;
    s[t] = v;
    __syncthreads();
    #pragma unroll
    for (int off = 1; off < 256; off <<= 1) {
        int add = (t >= off) ? s[t - off] : 0;
        __syncthreads();
        s[t] += add;
        __syncthreads();
    }
    if (i < N_NODES) g_rowptr[i] = s[t] - v;   // local exclusive
    if (t == 255) g_bsum[blockIdx.x] = s[255];
}

// Scan the 391 block sums (single block, 512 threads)
__global__ void scan2_kernel(int nblocks) {
    __shared__ int s[512];
    int t = threadIdx.x;
    int v = (t < nblocks) ? g_bsum[t] : 0;
    s[t] = v;
    __syncthreads();
    #pragma unroll
    for (int off = 1; off < 512; off <<= 1) {
        int add = (t >= off) ? s[t - off] : 0;
        __syncthreads();
        s[t] += add;
        __syncthreads();
    }
    if (t < nblocks) g_bsum[t] = s[t] - v;     // exclusive
}

__global__ void scan3_kernel() {
    int i = blockIdx.x * 256 + threadIdx.x;
    if (i < N_NODES) {
        int rp = g_rowptr[i] + g_bsum[blockIdx.x];
        g_rowptr[i] = rp;
        g_cursor[i] = rp;
        g_dinv[i] = rsqrtf((float)(g_cnt[i] + 1));  // +1 self loop; deg >= 1 always
    }
    if (i == 0) g_rowptr[N_NODES] = N_EDGES;
}

__global__ void fill_kernel(const int* __restrict__ row, const int* __restrict__ col) {
    int e = blockIdx.x * blockDim.x + threadIdx.x;
    if (e < N_EDGES) {
        int c = clampi(col[e], N_NODES);
        int p = atomicAdd(&g_cursor[c], 1);
        if (p >= 0 && p < N_EDGES) g_src[p] = clampi(row[e], N_NODES);
    }
}

// ---------------- GEMM: C[M,128] = A[M,128] @ W[128,128] ----------------
// Tile: 64 rows x 128 cols per block, 256 threads, 4x8 microtile.
#define GM 64
#define AP (GM + 4)

__global__ void gemm_kernel(const float* __restrict__ A, const float* __restrict__ W,
                            float* __restrict__ C) {
    extern __shared__ float smem[];
    float* Wst = smem;              // [128][128]
    float* Ast = smem + D * D;      // [128][AP] transposed: Ast[k][m]

    int t = threadIdx.x;
    int m0 = blockIdx.x * GM;

    // load W (flat copy, 4096 float4)
    const float4* W4 = (const float4*)W;
    float4* Wst4 = (float4*)Wst;
    #pragma unroll
    for (int it = 0; it < 16; it++) Wst4[it * 256 + t] = W4[it * 256 + t];

    // load A tile transposed (zero-pad tail rows)
    const float4* A4 = (const float4*)A;
    #pragma unroll
    for (int it = 0; it < 8; it++) {
        int idx = it * 256 + t;       // 0..2047 float4 slots
        int m = idx >> 5;             // 0..63
        int kq = idx & 31;            // float4 index along K
        float4 v = make_float4(0.f, 0.f, 0.f, 0.f);
        if (m0 + m < N_NODES) v = A4[(size_t)(m0 + m) * 32 + kq];
        Ast[(kq * 4 + 0) * AP + m] = v.x;
        Ast[(kq * 4 + 1) * AP + m] = v.y;
        Ast[(kq * 4 + 2) * AP + m] = v.z;
        Ast[(kq * 4 + 3) * AP + m] = v.w;
    }
    __syncthreads();

    int tx = t & 15, ty = t >> 4;
    int tx8 = tx * 8, ty4 = ty * 4;

    float acc[4][8];
    #pragma unroll
    for (int i = 0; i < 4; i++)
        #pragma unroll
        for (int j = 0; j < 8; j++) acc[i][j] = 0.f;

    #pragma unroll 8
    for (int k = 0; k < D; k++) {
        float4 a  = *(const float4*)&Ast[k * AP + ty4];
        float4 b0 = *(const float4*)&Wst[k * D + tx8];
        float4 b1 = *(const float4*)&Wst[k * D + tx8 + 4];
        float av[4] = {a.x, a.y, a.z, a.w};
        float bv[8] = {b0.x, b0.y, b0.z, b0.w, b1.x, b1.y, b1.z, b1.w};
        #pragma unroll
        for (int i = 0; i < 4; i++)
            #pragma unroll
            for (int j = 0; j < 8; j++) acc[i][j] += av[i] * bv[j];
    }

    #pragma unroll
    for (int i = 0; i < 4; i++) {
        int m = m0 + ty4 + i;
        if (m < N_NODES) {
            float4* Cp = (float4*)&C[(size_t)m * D + tx8];
            Cp[0] = make_float4(acc[i][0], acc[i][1], acc[i][2], acc[i][3]);
            Cp[1] = make_float4(acc[i][4], acc[i][5], acc[i][6], acc[i][7]);
        }
    }
}

// ---------------- Aggregation: warp per node, gather incoming edges ----------------
// out[v] = relu?( dinv[v] * sum_e dinv[src] * xw[src] + dinv[v]^2 * xw[v] + b )
__global__ void aggregate_kernel(const float* __restrict__ xw, const float* __restrict__ bias,
                                 float* __restrict__ hout, int do_relu) {
    int gw = (blockIdx.x * blockDim.x + threadIdx.x) >> 5;
    int lane = threadIdx.x & 31;
    if (gw >= N_NODES) return;
    int v = gw;
    int beg = g_rowptr[v];
    int end = g_rowptr[v + 1];

    const float4* xw4 = (const float4*)xw;
    float ax = 0.f, ay = 0.f, az = 0.f, aw = 0.f;
    float bx = 0.f, by = 0.f, bz = 0.f, bw = 0.f;

    int p = beg;
    for (; p + 2 <= end; p += 2) {
        int s0 = g_src[p];
        int s1 = g_src[p + 1];
        float w0 = g_dinv[s0];
        float w1 = g_dinv[s1];
        float4 x0 = xw4[(size_t)s0 * 32 + lane];
        float4 x1 = xw4[(size_t)s1 * 32 + lane];
        ax += w0 * x0.x; ay += w0 * x0.y; az += w0 * x0.z; aw += w0 * x0.w;
        bx += w1 * x1.x; by += w1 * x1.y; bz += w1 * x1.z; bw += w1 * x1.w;
    }
    if (p < end) {
        int s0 = g_src[p];
        float w0 = g_dinv[s0];
        float4 x0 = xw4[(size_t)s0 * 32 + lane];
        ax += w0 * x0.x; ay += w0 * x0.y; az += w0 * x0.z; aw += w0 * x0.w;
    }

    float dv = g_dinv[v];
    float dv2 = dv * dv;
    float4 sf = xw4[(size_t)v * 32 + lane];
    float4 b4 = ((const float4*)bias)[lane];

    float rx = dv * (ax + bx) + dv2 * sf.x + b4.x;
    float ry = dv * (ay + by) + dv2 * sf.y + b4.y;
    float rz = dv * (az + bz) + dv2 * sf.z + b4.z;
    float rw = dv * (aw + bw) + dv2 * sf.w + b4.w;

    if (do_relu) {
        rx = fmaxf(rx, 0.f); ry = fmaxf(ry, 0.f);
        rz = fmaxf(rz, 0.f); rw = fmaxf(rw, 0.f);
    }
    ((float4*)hout)[(size_t)v * 32 + lane] = make_float4(rx, ry, rz, rw);
}

// ---------------- Pool (mean by graph, batch sorted) + MLP head ----------------
__global__ void pool_mlp_kernel(const float* __restrict__ h, const int* __restrict__ batch,
                                const float* __restrict__ w1, const float* __restrict__ b1,
                                const float* __restrict__ w2, const float* __restrict__ b2,
                                float* __restrict__ out) {
    int g = blockIdx.x;
    int t = threadIdx.x;   // 128 threads

    __shared__ int s_bounds[2];
    if (t < 2) {
        int target = g + t;
        int lo = 0, hi = N_NODES;
        while (lo < hi) {
            int mid = (lo + hi) >> 1;
            if (batch[mid] < target) lo = mid + 1; else hi = mid;
        }
        s_bounds[t] = lo;
    }
    __syncthreads();
    int beg = s_bounds[0], end = s_bounds[1];

    float sum = 0.f;
    for (int n = beg; n < end; n++) sum += h[(size_t)n * D + t];
    float cnt = fmaxf((float)(end - beg), 1.0f);

    __shared__ float pooled[D];
    __shared__ float hid[100];
    pooled[t] = sum / cnt;
    __syncthreads();

    if (t < 100) {
        float a = b1[t];
        #pragma unroll 8
        for (int k = 0; k < D; k++) a += pooled[k] * w1[k * 100 + t];
        hid[t] = fmaxf(a, 0.f);
    }
    __syncthreads();

    if (t < 4) {
        float a = b2[t];
        #pragma unroll
        for (int k = 0; k < 100; k++) a += hid[k] * w2[k * 4 + t];
        out[g * 4 + t] = a;
    }
}

// ---------------- launch ----------------
extern "C" void kernel_launch(void* const* d_in, const int* in_sizes, int n_in,
                              void* d_out, int out_size) {
    // Bind inputs by UNIQUE element count (robust to metadata ordering):
    //   x: 12,800,000 f32   Ws: 65,536 f32    bs: 512 f32
    //   mlp_w1: 12,800 f32  mlp_b1: 100 f32   mlp_w2: 400 f32  mlp_b2: 4 f32
    //   edge_index: 3,200,000 i32 (JAX x64 disabled => int32)   batch: 100,000 i32
    const float *x = 0, *Ws = 0, *bs = 0, *w1 = 0, *b1 = 0, *w2 = 0, *b2 = 0;
    const int *eidx = 0, *batch = 0;
    for (int i = 0; i < n_in; i++) {
        switch (in_sizes[i]) {
            case 12800000: x     = (const float*)d_in[i]; break;
            case 65536:    Ws    = (const float*)d_in[i]; break;
            case 512:      bs    = (const float*)d_in[i]; break;
            case 12800:    w1    = (const float*)d_in[i]; break;
            case 100:      b1    = (const float*)d_in[i]; break;
            case 400:      w2    = (const float*)d_in[i]; break;
            case 4:        b2    = (const float*)d_in[i]; break;
            case 3200000:  eidx  = (const int*)d_in[i]; break;
            case 100000:   batch = (const int*)d_in[i]; break;
            default: break;
        }
    }
    float* out = (float*)d_out;

    const int* row = eidx;              // edge_index[0] = source
    const int* col = eidx + N_EDGES;    // edge_index[1] = target

    float *p_xw = nullptr, *p_h = nullptr;
    cudaGetSymbolAddress((void**)&p_xw, g_xw);
    cudaGetSymbolAddress((void**)&p_h,  g_h);

    const int NB_NODE = (N_NODES + 255) / 256;      // 391
    const int NB_EDGE = (N_EDGES + 255) / 256;      // 6250
    const int GEMM_BLOCKS = (N_NODES + GM - 1) / GM; // 1563
    const int GEMM_SMEM = (D * D + D * AP) * (int)sizeof(float); // ~98 KB
    const int AGG_BLOCKS = (N_NODES * 32 + 255) / 256; // warp per node

    cudaFuncSetAttribute(gemm_kernel, cudaFuncAttributeMaxDynamicSharedMemorySize, GEMM_SMEM);

    // CSR build (by destination) + degree/norm
    zero_cnt_kernel<<<NB_NODE, 256>>>();
    count_kernel<<<NB_EDGE, 256>>>(col);
    scan1_kernel<<<NB_NODE, 256>>>();
    scan2_kernel<<<1, 512>>>(NB_NODE);
    scan3_kernel<<<NB_NODE, 256>>>();
    fill_kernel<<<NB_EDGE, 256>>>(row, col);

    // 4 GCN layers (ReLU fused into aggregation for layers 0..2)
    const float* hin = x;
    for (int l = 0; l < N_LAYERS; l++) {
        gemm_kernel<<<GEMM_BLOCKS, 256, GEMM_SMEM>>>(hin, Ws + (size_t)l * D * D, p_xw);
        aggregate_kernel<<<AGG_BLOCKS, 256>>>(p_xw, bs + (size_t)l * D, p_h,
                                              (l < N_LAYERS - 1) ? 1 : 0);
        hin = p_h;
    }

    // mean pool + MLP head
    pool_mlp_kernel<<<N_GRAPHS, 128>>>(p_h, batch, w1, b1, w2, b2, out);
}

// round 6
// speedup vs baseline: 1.7030x; 1.7030x over previous
#include <cuda_runtime.h>
#include <cuda_bf16.h>
#include <cstdint>

#define N_NODES 100000
#define N_EDGES 1600000
#define D 128
#define N_LAYERS 4
#define N_GRAPHS 512

// ---------------- device scratch (no allocations allowed) ----------------
__device__ float g_xw[N_NODES * D];       // XW buffer (51.2 MB)
__device__ float g_h[N_NODES * D];        // aggregated hidden (51.2 MB)
__device__ float g_dinv[N_NODES];
__device__ int   g_cnt[N_NODES];
__device__ int   g_rowptr[N_NODES + 1];
__device__ int   g_cursor[N_NODES];
__device__ int   g_bsum[512];
__device__ int   g_src[N_EDGES];          // CSR (by destination) source ids
// W^T split images: [n][k] bf16, plain 128-contiguous rows
__device__ __nv_bfloat16 g_whi[N_LAYERS * D * D];
__device__ __nv_bfloat16 g_wlo[N_LAYERS * D * D];

// ---------------- CSR build ----------------
__global__ void zero_cnt_kernel() {
    int i = blockIdx.x * blockDim.x + threadIdx.x;
    if (i < N_NODES) g_cnt[i] = 0;
}

__device__ __forceinline__ int clampi(int v, int hi) {
    return v < 0 ? 0 : (v >= hi ? hi - 1 : v);
}

__global__ void count_kernel(const int* __restrict__ col) {
    int e = blockIdx.x * blockDim.x + threadIdx.x;
    if (e < N_EDGES) atomicAdd(&g_cnt[clampi(col[e], N_NODES)], 1);
}

__global__ void scan1_kernel() {
    __shared__ int s[256];
    int t = threadIdx.x;
    int i = blockIdx.x * 256 + t;
    int v = (i < N_NODES) ? g_cnt[i] : 0;
    s[t] = v;
    __syncthreads();
    #pragma unroll
    for (int off = 1; off < 256; off <<= 1) {
        int add = (t >= off) ? s[t - off] : 0;
        __syncthreads();
        s[t] += add;
        __syncthreads();
    }
    if (i < N_NODES) g_rowptr[i] = s[t] - v;
    if (t == 255) g_bsum[blockIdx.x] = s[255];
}

__global__ void scan2_kernel(int nblocks) {
    __shared__ int s[512];
    int t = threadIdx.x;
    int v = (t < nblocks) ? g_bsum[t] : 0;
    s[t] = v;
    __syncthreads();
    #pragma unroll
    for (int off = 1; off < 512; off <<= 1) {
        int add = (t >= off) ? s[t - off] : 0;
        __syncthreads();
        s[t] += add;
        __syncthreads();
    }
    if (t < nblocks) g_bsum[t] = s[t] - v;
}

__global__ void scan3_kernel() {
    int i = blockIdx.x * 256 + threadIdx.x;
    if (i < N_NODES) {
        int rp = g_rowptr[i] + g_bsum[blockIdx.x];
        g_rowptr[i] = rp;
        g_cursor[i] = rp;
        g_dinv[i] = rsqrtf((float)(g_cnt[i] + 1));
    }
    if (i == 0) g_rowptr[N_NODES] = N_EDGES;
}

__global__ void fill_kernel(const int* __restrict__ row, const int* __restrict__ col) {
    int e = blockIdx.x * blockDim.x + threadIdx.x;
    if (e < N_EDGES) {
        int c = clampi(col[e], N_NODES);
        int p = atomicAdd(&g_cursor[c], 1);
        if (p >= 0 && p < N_EDGES) g_src[p] = clampi(row[e], N_NODES);
    }
}

// ---------------- W preprocessing: split + transpose ----------------
__global__ void wsplit_kernel(const float* __restrict__ Ws) {
    int l = blockIdx.x;
    __nv_bfloat16* hi = g_whi + l * D * D;
    __nv_bfloat16* lo = g_wlo + l * D * D;
    const float* W = Ws + l * D * D;
    for (int idx = threadIdx.x; idx < D * D; idx += blockDim.x) {
        int n = idx >> 7, k = idx & 127;
        float w = W[k * D + n];                    // transpose: image[n][k] = W[k][n]
        __nv_bfloat16 hb = __float2bfloat16_rn(w);
        __nv_bfloat16 lb = __float2bfloat16_rn(w - __bfloat162float(hb));
        hi[idx] = hb;
        lo[idx] = lb;
    }
}

// ---------------- Tensor-core GEMM via mma.sync (split-bf16, 3 products) ----------------
// C[128,128] tile = A @ W.  8 warps; warp w owns rows w*16..w*16+15 x all 128 cols.
// Smem rows padded to 136 bf16 (272 B) => conflict-free fragment LDS.
#define PAD 136
#define SM_AHI 0
#define SM_ALO (SM_AHI + D * PAD * 2)          // 34816
#define SM_BHI (SM_ALO + D * PAD * 2)
#define SM_BLO (SM_BHI + D * PAD * 2)
#define GEMM_SMEM (SM_BLO + D * PAD * 2)       // 139264 B

__device__ __forceinline__ void mma16816(float c[4], const uint32_t a[4], const uint32_t b[2]) {
    asm volatile(
        "mma.sync.aligned.m16n8k16.row.col.f32.bf16.bf16.f32 "
        "{%0,%1,%2,%3}, {%4,%5,%6,%7}, {%8,%9}, {%0,%1,%2,%3};"
        : "+f"(c[0]), "+f"(c[1]), "+f"(c[2]), "+f"(c[3])
        : "r"(a[0]), "r"(a[1]), "r"(a[2]), "r"(a[3]), "r"(b[0]), "r"(b[1]));
}

__global__ void __launch_bounds__(256, 1)
gemm_mma_kernel(const float* __restrict__ A,
                const __nv_bfloat16* __restrict__ whi,
                const __nv_bfloat16* __restrict__ wlo,
                float* __restrict__ C) {
    extern __shared__ char smem[];
    int t = threadIdx.x;
    int warp = t >> 5, lane = t & 31;
    int m0 = blockIdx.x * 128;

    // ---- load W^T images into padded smem (16B chunks) ----
    {
        const uint4* hsrc = (const uint4*)whi;   // row n: 256 B = 16 uint4
        const uint4* lsrc = (const uint4*)wlo;
        #pragma unroll
        for (int i = 0; i < 8; i++) {
            int idx = i * 256 + t;               // 2048 chunks
            int n = idx >> 4, c = idx & 15;
            *(uint4*)(smem + SM_BHI + n * (PAD * 2) + c * 16) = hsrc[n * 16 + c];
            *(uint4*)(smem + SM_BLO + n * (PAD * 2) + c * 16) = lsrc[n * 16 + c];
        }
    }

    // ---- load A tile fp32, split hi/lo, store padded ----
    {
        const float4* A4 = (const float4*)A;
        #pragma unroll
        for (int i = 0; i < 16; i++) {
            int idx = i * 256 + t;               // 4096 float4 slots
            int row = idx >> 5, kq = idx & 31;
            float4 v = make_float4(0.f, 0.f, 0.f, 0.f);
            if (m0 + row < N_NODES) v = A4[(size_t)(m0 + row) * 32 + kq];
            __nv_bfloat16 h0 = __float2bfloat16_rn(v.x), h1 = __float2bfloat16_rn(v.y);
            __nv_bfloat16 h2 = __float2bfloat16_rn(v.z), h3 = __float2bfloat16_rn(v.w);
            __nv_bfloat16 l0 = __float2bfloat16_rn(v.x - __bfloat162float(h0));
            __nv_bfloat16 l1 = __float2bfloat16_rn(v.y - __bfloat162float(h1));
            __nv_bfloat16 l2 = __float2bfloat16_rn(v.z - __bfloat162float(h2));
            __nv_bfloat16 l3 = __float2bfloat16_rn(v.w - __bfloat162float(h3));
            uint2 hp = make_uint2(((uint32_t)__bfloat16_as_ushort(h1) << 16) | __bfloat16_as_ushort(h0),
                                  ((uint32_t)__bfloat16_as_ushort(h3) << 16) | __bfloat16_as_ushort(h2));
            uint2 lp = make_uint2(((uint32_t)__bfloat16_as_ushort(l1) << 16) | __bfloat16_as_ushort(l0),
                                  ((uint32_t)__bfloat16_as_ushort(l3) << 16) | __bfloat16_as_ushort(l2));
            *(uint2*)(smem + SM_AHI + row * (PAD * 2) + kq * 8) = hp;
            *(uint2*)(smem + SM_ALO + row * (PAD * 2) + kq * 8) = lp;
        }
    }
    __syncthreads();

    // ---- compute ----
    int g = lane >> 2;            // 0..7
    int tg = lane & 3;            // 0..3
    int bm = warp * 16;           // warp's row block

    float acc[16][4];
    #pragma unroll
    for (int nt = 0; nt < 16; nt++)
        #pragma unroll
        for (int j = 0; j < 4; j++) acc[nt][j] = 0.f;

    const char* pAhi = smem + SM_AHI + (bm + g) * (PAD * 2) + tg * 4;
    const char* pAlo = smem + SM_ALO + (bm + g) * (PAD * 2) + tg * 4;
    const char* pBhi = smem + SM_BHI + g * (PAD * 2) + tg * 4;
    const char* pBlo = smem + SM_BLO + g * (PAD * 2) + tg * 4;

    #pragma unroll
    for (int s = 0; s < 8; s++) {
        int k0b = s * 32;                          // k0 in bytes (16 bf16)
        uint32_t ahi[4], alo[4];
        ahi[0] = *(const uint32_t*)(pAhi + k0b);
        ahi[1] = *(const uint32_t*)(pAhi + k0b + 8 * (PAD * 2));
        ahi[2] = *(const uint32_t*)(pAhi + k0b + 16);
        ahi[3] = *(const uint32_t*)(pAhi + k0b + 8 * (PAD * 2) + 16);
        alo[0] = *(const uint32_t*)(pAlo + k0b);
        alo[1] = *(const uint32_t*)(pAlo + k0b + 8 * (PAD * 2));
        alo[2] = *(const uint32_t*)(pAlo + k0b + 16);
        alo[3] = *(const uint32_t*)(pAlo + k0b + 8 * (PAD * 2) + 16);

        #pragma unroll
        for (int nt = 0; nt < 16; nt++) {
            uint32_t bhi[2], blo[2];
            const char* bh = pBhi + nt * 8 * (PAD * 2) + k0b;
            const char* bl = pBlo + nt * 8 * (PAD * 2) + k0b;
            bhi[0] = *(const uint32_t*)(bh);
            bhi[1] = *(const uint32_t*)(bh + 16);
            blo[0] = *(const uint32_t*)(bl);
            blo[1] = *(const uint32_t*)(bl + 16);
            mma16816(acc[nt], ahi, bhi);
            mma16816(acc[nt], ahi, blo);
            mma16816(acc[nt], alo, bhi);
        }
    }

    // ---- epilogue: direct global stores (float2 per pair) ----
    int r0 = m0 + bm + g;
    int r1 = r0 + 8;
    #pragma unroll
    for (int nt = 0; nt < 16; nt++) {
        int cb = nt * 8 + tg * 2;
        if (r0 < N_NODES)
            *(float2*)&C[(size_t)r0 * D + cb] = make_float2(acc[nt][0], acc[nt][1]);
        if (r1 < N_NODES)
            *(float2*)&C[(size_t)r1 * D + cb] = make_float2(acc[nt][2], acc[nt][3]);
    }
}

// ---------------- Aggregation: warp per node, gather incoming edges ----------------
__global__ void aggregate_kernel(const float* __restrict__ xw, const float* __restrict__ bias,
                                 float* __restrict__ hout, int do_relu) {
    int gw = (blockIdx.x * blockDim.x + threadIdx.x) >> 5;
    int lane = threadIdx.x & 31;
    if (gw >= N_NODES) return;
    int v = gw;
    int beg = g_rowptr[v];
    int end = g_rowptr[v + 1];

    const float4* xw4 = (const float4*)xw;
    float ax = 0.f, ay = 0.f, az = 0.f, aw = 0.f;
    float bx = 0.f, by = 0.f, bz = 0.f, bw = 0.f;

    int p = beg;
    for (; p + 2 <= end; p += 2) {
        int s0 = g_src[p];
        int s1 = g_src[p + 1];
        float w0 = g_dinv[s0];
        float w1 = g_dinv[s1];
        float4 x0 = xw4[(size_t)s0 * 32 + lane];
        float4 x1 = xw4[(size_t)s1 * 32 + lane];
        ax += w0 * x0.x; ay += w0 * x0.y; az += w0 * x0.z; aw += w0 * x0.w;
        bx += w1 * x1.x; by += w1 * x1.y; bz += w1 * x1.z; bw += w1 * x1.w;
    }
    if (p < end) {
        int s0 = g_src[p];
        float w0 = g_dinv[s0];
        float4 x0 = xw4[(size_t)s0 * 32 + lane];
        ax += w0 * x0.x; ay += w0 * x0.y; az += w0 * x0.z; aw += w0 * x0.w;
    }

    float dv = g_dinv[v];
    float dv2 = dv * dv;
    float4 sf = xw4[(size_t)v * 32 + lane];
    float4 b4 = ((const float4*)bias)[lane];

    float rx = dv * (ax + bx) + dv2 * sf.x + b4.x;
    float ry = dv * (ay + by) + dv2 * sf.y + b4.y;
    float rz = dv * (az + bz) + dv2 * sf.z + b4.z;
    float rw = dv * (aw + bw) + dv2 * sf.w + b4.w;

    if (do_relu) {
        rx = fmaxf(rx, 0.f); ry = fmaxf(ry, 0.f);
        rz = fmaxf(rz, 0.f); rw = fmaxf(rw, 0.f);
    }
    ((float4*)hout)[(size_t)v * 32 + lane] = make_float4(rx, ry, rz, rw);
}

// ---------------- Pool + MLP head ----------------
__global__ void pool_mlp_kernel(const float* __restrict__ h, const int* __restrict__ batch,
                                const float* __restrict__ w1, const float* __restrict__ b1,
                                const float* __restrict__ w2, const float* __restrict__ b2,
                                float* __restrict__ out) {
    int g = blockIdx.x;
    int t = threadIdx.x;   // 128 threads

    __shared__ int s_bounds[2];
    if (t < 2) {
        int target = g + t;
        int lo = 0, hi = N_NODES;
        while (lo < hi) {
            int mid = (lo + hi) >> 1;
            if (batch[mid] < target) lo = mid + 1; else hi = mid;
        }
        s_bounds[t] = lo;
    }
    __syncthreads();
    int beg = s_bounds[0], end = s_bounds[1];

    float sum = 0.f;
    for (int n = beg; n < end; n++) sum += h[(size_t)n * D + t];
    float cnt = fmaxf((float)(end - beg), 1.0f);

    __shared__ float pooled[D];
    __shared__ float hid[100];
    pooled[t] = sum / cnt;
    __syncthreads();

    if (t < 100) {
        float a = b1[t];
        #pragma unroll 8
        for (int k = 0; k < D; k++) a += pooled[k] * w1[k * 100 + t];
        hid[t] = fmaxf(a, 0.f);
    }
    __syncthreads();

    if (t < 4) {
        float a = b2[t];
        #pragma unroll
        for (int k = 0; k < 100; k++) a += hid[k] * w2[k * 4 + t];
        out[g * 4 + t] = a;
    }
}

// ---------------- launch ----------------
extern "C" void kernel_launch(void* const* d_in, const int* in_sizes, int n_in,
                              void* d_out, int out_size) {
    const float *x = 0, *Ws = 0, *bs = 0, *w1 = 0, *b1 = 0, *w2 = 0, *b2 = 0;
    const int *eidx = 0, *batch = 0;
    for (int i = 0; i < n_in; i++) {
        switch (in_sizes[i]) {
            case 12800000: x     = (const float*)d_in[i]; break;
            case 65536:    Ws    = (const float*)d_in[i]; break;
            case 512:      bs    = (const float*)d_in[i]; break;
            case 12800:    w1    = (const float*)d_in[i]; break;
            case 100:      b1    = (const float*)d_in[i]; break;
            case 400:      w2    = (const float*)d_in[i]; break;
            case 4:        b2    = (const float*)d_in[i]; break;
            case 3200000:  eidx  = (const int*)d_in[i]; break;
            case 100000:   batch = (const int*)d_in[i]; break;
            default: break;
        }
    }
    float* out = (float*)d_out;

    const int* row = eidx;              // edge_index[0] = source
    const int* col = eidx + N_EDGES;    // edge_index[1] = target

    float *p_xw = nullptr, *p_h = nullptr;
    __nv_bfloat16 *p_whi = nullptr, *p_wlo = nullptr;
    cudaGetSymbolAddress((void**)&p_xw,  g_xw);
    cudaGetSymbolAddress((void**)&p_h,   g_h);
    cudaGetSymbolAddress((void**)&p_whi, g_whi);
    cudaGetSymbolAddress((void**)&p_wlo, g_wlo);

    const int NB_NODE = (N_NODES + 255) / 256;        // 391
    const int NB_EDGE = (N_EDGES + 255) / 256;        // 6250
    const int TC_BLOCKS = (N_NODES + 127) / 128;      // 782
    const int AGG_BLOCKS = (N_NODES * 32 + 255) / 256;

    cudaFuncSetAttribute(gemm_mma_kernel, cudaFuncAttributeMaxDynamicSharedMemorySize, GEMM_SMEM);

    // CSR build (by destination) + degree/norm; W split images
    zero_cnt_kernel<<<NB_NODE, 256>>>();
    count_kernel<<<NB_EDGE, 256>>>(col);
    scan1_kernel<<<NB_NODE, 256>>>();
    scan2_kernel<<<1, 512>>>(NB_NODE);
    scan3_kernel<<<NB_NODE, 256>>>();
    fill_kernel<<<NB_EDGE, 256>>>(row, col);
    wsplit_kernel<<<N_LAYERS, 256>>>(Ws);

    // 4 GCN layers (ReLU fused into aggregation for layers 0..2)
    const float* hin = x;
    for (int l = 0; l < N_LAYERS; l++) {
        gemm_mma_kernel<<<TC_BLOCKS, 256, GEMM_SMEM>>>(hin, p_whi + (size_t)l * D * D,
                                                       p_wlo + (size_t)l * D * D, p_xw);
        aggregate_kernel<<<AGG_BLOCKS, 256>>>(p_xw, bs + (size_t)l * D, p_h,
                                              (l < N_LAYERS - 1) ? 1 : 0);
        hin = p_h;
    }

    // mean pool + MLP head
    pool_mlp_kernel<<<N_GRAPHS, 128>>>(p_h, batch, w1, b1, w2, b2, out);
}